// round 4
// baseline (speedup 1.0000x reference)
#include <cuda_runtime.h>
#include <cstddef>

#define DIMM    768
#define MTOK    4096      // B*N
#define NSEQ    1024
#define NHEADS  12
#define DHEAD   64
#define FFI     2048
#define BHTOT   48        // B*HEADS

// ---------------- scratch (static device globals; no allocation) -------------
__device__ float g_h [MTOK * DIMM];          // LN output
__device__ float g_q [MTOK * DIMM];          // q = h @ wq
__device__ float g_kv[MTOK * 2 * DIMM];      // kv = x @ wkv
__device__ float g_qt[BHTOT * NSEQ * DHEAD]; // Q in (b,h,n,d)
__device__ float g_kt[BHTOT * NSEQ * DHEAD]; // K in (b,h,n,d)
__device__ float g_vt[BHTOT * NSEQ * DHEAD]; // V in (b,h,n,d)
__device__ float g_o [MTOK * DIMM];          // attention output (b,n,inner)
__device__ float g_u [MTOK * 2 * FFI];       // wff1 output
__device__ float g_g [MTOK * FFI];           // gated

// ------------------------------- LayerNorm -----------------------------------
// one block per row (768 = 3*256)
__global__ void __launch_bounds__(256) ln_kernel(
    const float* __restrict__ x, const float* __restrict__ gamma,
    const float* __restrict__ beta, float* __restrict__ out)
{
    int row = blockIdx.x;
    int tid = threadIdx.x;
    const float* xr = x + (size_t)row * DIMM;
    float v0 = xr[tid], v1 = xr[tid + 256], v2 = xr[tid + 512];
    float s  = v0 + v1 + v2;
    float sq = v0 * v0 + v1 * v1 + v2 * v2;
#pragma unroll
    for (int o = 16; o > 0; o >>= 1) {
        s  += __shfl_xor_sync(0xffffffffu, s, o);
        sq += __shfl_xor_sync(0xffffffffu, sq, o);
    }
    __shared__ float red[16];
    int w = tid >> 5;
    if ((tid & 31) == 0) { red[w] = s; red[w + 8] = sq; }
    __syncthreads();
    float ts = 0.f, tq = 0.f;
#pragma unroll
    for (int i = 0; i < 8; i++) { ts += red[i]; tq += red[i + 8]; }
    float mu  = ts * (1.0f / 768.0f);
    float var = tq * (1.0f / 768.0f) - mu * mu;
    float inv = rsqrtf(var + 1e-5f);
    float* orow = out + (size_t)row * DIMM;
    float b0 = beta ? beta[tid]       : 0.f;
    float b1 = beta ? beta[tid + 256] : 0.f;
    float b2 = beta ? beta[tid + 512] : 0.f;
    orow[tid]       = (v0 - mu) * inv * gamma[tid]       + b0;
    orow[tid + 256] = (v1 - mu) * inv * gamma[tid + 256] + b1;
    orow[tid + 512] = (v2 - mu) * inv * gamma[tid + 512] + b2;
}

// ------------------------------- SGEMM ---------------------------------------
// C[M,N] = A[M,K] @ B[K,N] (+ res). 128x128 block tile, BK=16, 256 threads,
// 8x8 per thread. Requires M%128==0, N%128==0, K%16==0 (all shapes satisfy).
#define BM 128
#define BN 128
#define BKK 16
__global__ void __launch_bounds__(256) sgemm_kernel(
    const float* __restrict__ A, const float* __restrict__ B,
    const float* __restrict__ res, float* __restrict__ C,
    int M, int N, int K)
{
    __shared__ __align__(16) float As[BKK][BM];
    __shared__ __align__(16) float Bs[BKK][BN];
    int tid = threadIdx.x;
    int bm = blockIdx.y * BM;
    int bn = blockIdx.x * BN;
    int tx = tid & 15;
    int ty = tid >> 4;

    float acc[8][8];
#pragma unroll
    for (int i = 0; i < 8; i++)
#pragma unroll
        for (int j = 0; j < 8; j++) acc[i][j] = 0.f;

    const float* Ab = A + (size_t)bm * K;
    const float* Bb = B + bn;

    for (int k0 = 0; k0 < K; k0 += BKK) {
#pragma unroll
        for (int i = 0; i < 2; i++) {
            int id = tid + i * 256;        // 512 float4 loads cover 128x16
            int ar = id >> 2;              // 0..127
            int ac = (id & 3) << 2;        // 0,4,8,12
            float4 v = *reinterpret_cast<const float4*>(Ab + (size_t)ar * K + k0 + ac);
            As[ac + 0][ar] = v.x; As[ac + 1][ar] = v.y;
            As[ac + 2][ar] = v.z; As[ac + 3][ar] = v.w;
        }
#pragma unroll
        for (int i = 0; i < 2; i++) {
            int id = tid + i * 256;
            int br = id >> 5;              // 0..15
            int bc = (id & 31) << 2;       // 0..124
            *reinterpret_cast<float4*>(&Bs[br][bc]) =
                *reinterpret_cast<const float4*>(Bb + (size_t)(k0 + br) * N + bc);
        }
        __syncthreads();
#pragma unroll
        for (int k = 0; k < BKK; k++) {
            float a[8], b[8];
            *reinterpret_cast<float4*>(a)     = *reinterpret_cast<float4*>(&As[k][ty * 8]);
            *reinterpret_cast<float4*>(a + 4) = *reinterpret_cast<float4*>(&As[k][ty * 8 + 4]);
            *reinterpret_cast<float4*>(b)     = *reinterpret_cast<float4*>(&Bs[k][tx * 8]);
            *reinterpret_cast<float4*>(b + 4) = *reinterpret_cast<float4*>(&Bs[k][tx * 8 + 4]);
#pragma unroll
            for (int i = 0; i < 8; i++)
#pragma unroll
                for (int j = 0; j < 8; j++)
                    acc[i][j] = fmaf(a[i], b[j], acc[i][j]);
        }
        __syncthreads();
    }
#pragma unroll
    for (int i = 0; i < 8; i++) {
        size_t row = (size_t)(bm + ty * 8 + i);
#pragma unroll
        for (int j = 0; j < 8; j += 4) {
            size_t idx = row * N + bn + tx * 8 + j;
            float4 o;
            o.x = acc[i][j]; o.y = acc[i][j + 1]; o.z = acc[i][j + 2]; o.w = acc[i][j + 3];
            if (res) {
                float4 r = *reinterpret_cast<const float4*>(res + idx);
                o.x += r.x; o.y += r.y; o.z += r.z; o.w += r.w;
            }
            *reinterpret_cast<float4*>(C + idx) = o;
        }
    }
}

// --------------------- RoPE + l2norm + scale + transpose ---------------------
// block = one (token-row, head); 64 threads = dh lanes.
// src row layout: [..., h*64+d] with row stride srcStride.
// dst: (b, h, n, d)
__global__ void __launch_bounds__(64) rope_norm_kernel(
    const float* __restrict__ src, int srcStride,
    const float* __restrict__ scale, float* __restrict__ dst)
{
    int row = blockIdx.x;            // b*1024 + n
    int h   = blockIdx.y;
    int d   = threadIdx.x;
    int n   = row & 1023;
    int b   = row >> 10;
    float v = src[(size_t)row * srcStride + h * DHEAD + d];

    // 2D rope: pair j = d/2; freq index t = j/2; j even -> x (n%32), odd -> y (n/32)
    int j = d >> 1;
    int t = j >> 1;
    float p = (j & 1) ? (float)(n >> 5) : (float)(n & 31);
    float freq = exp2f(-0.830482024f * (float)t);   // 10000^(-t/16)
    float ang = p * freq;
    float c = cosf(ang), s = sinf(ang);
    float other = __shfl_xor_sync(0xffffffffu, v, 1);
    float out = (d & 1) ? (other * s + v * c) : (v * c - other * s);

    // l2 norm over the 64-wide head dim (2 warps)
    float ss = out * out;
#pragma unroll
    for (int o = 16; o > 0; o >>= 1) ss += __shfl_xor_sync(0xffffffffu, ss, o);
    __shared__ float wsum[2];
    if ((d & 31) == 0) wsum[d >> 5] = ss;
    __syncthreads();
    float tot = wsum[0] + wsum[1];
    float inv = 1.0f / fmaxf(sqrtf(tot), 1e-12f);
    out = out * inv * scale[d];
    dst[(((size_t)(b * NHEADS + h)) * NSEQ + n) * DHEAD + d] = out;
}

// ---------------------------- V transpose ------------------------------------
__global__ void __launch_bounds__(256) vtrans_kernel(
    const float* __restrict__ kv, float* __restrict__ V)
{
    int idx = blockIdx.x * 256 + threadIdx.x;  // 0 .. 4096*768-1
    int row = idx / DIMM;
    int c   = idx - row * DIMM;
    int n = row & 1023, b = row >> 10;
    int h = c >> 6, d = c & 63;
    V[(((size_t)(b * NHEADS + h)) * NSEQ + n) * DHEAD + d] =
        kv[(size_t)row * (2 * DIMM) + DIMM + c];
}

// ------------------------- Flash attention ------------------------------------
// one block = (bh, 64 queries); 128 threads (ty=tid>>3 rows x4, tx=tid&7 cols x8)
__global__ void __launch_bounds__(128) attn_kernel(
    const float* __restrict__ Q, const float* __restrict__ K,
    const float* __restrict__ V, float* __restrict__ O)
{
    __shared__ __align__(16) float Qt[64][64];   // [d][q]  (pre-scaled by 8)
    __shared__ __align__(16) float Kt[64][64];   // [d][k]; reused as P[k][q]
    __shared__ __align__(16) float Vs[64][64];   // [k][d]

    int tid = threadIdx.x;
    int bh  = blockIdx.y;
    int q0  = blockIdx.x * 64;
    const float* Qg = Q + ((size_t)bh * NSEQ + q0) * DHEAD;
    const float* Kg = K + (size_t)bh * NSEQ * DHEAD;
    const float* Vg = V + (size_t)bh * NSEQ * DHEAD;
    int ty = tid >> 3;
    int tx = tid & 7;

    // load Q tile transposed & scaled
#pragma unroll
    for (int i = 0; i < 8; i++) {
        int id = tid + i * 128;
        int r  = id & 63;
        int c4 = (id >> 6) << 2;
        float4 v = *reinterpret_cast<const float4*>(Qg + r * 64 + c4);
        Qt[c4 + 0][r] = v.x * 8.0f;
        Qt[c4 + 1][r] = v.y * 8.0f;
        Qt[c4 + 2][r] = v.z * 8.0f;
        Qt[c4 + 3][r] = v.w * 8.0f;
    }
    float m[4], l[4], o[4][8];
#pragma unroll
    for (int i = 0; i < 4; i++) {
        m[i] = -1e30f; l[i] = 0.f;
#pragma unroll
        for (int j = 0; j < 8; j++) o[i][j] = 0.f;
    }
    __syncthreads();

    for (int kt = 0; kt < 16; kt++) {
        const float* Kgt = Kg + kt * 64 * 64;
        const float* Vgt = Vg + kt * 64 * 64;
#pragma unroll
        for (int i = 0; i < 8; i++) {
            int id = tid + i * 128;
            int r  = id & 63;
            int c4 = (id >> 6) << 2;
            float4 kk = *reinterpret_cast<const float4*>(Kgt + r * 64 + c4);
            Kt[c4 + 0][r] = kk.x; Kt[c4 + 1][r] = kk.y;
            Kt[c4 + 2][r] = kk.z; Kt[c4 + 3][r] = kk.w;
            int r2 = id >> 4;
            int d4 = (id & 15) << 2;
            *reinterpret_cast<float4*>(&Vs[r2][d4]) =
                *reinterpret_cast<const float4*>(Vgt + r2 * 64 + d4);
        }
        __syncthreads();

        // S = (8*Q) K^T
        float s[4][8];
#pragma unroll
        for (int i = 0; i < 4; i++)
#pragma unroll
            for (int j = 0; j < 8; j++) s[i][j] = 0.f;
#pragma unroll 4
        for (int d = 0; d < 64; d++) {
            float qv[4];
#pragma unroll
            for (int i = 0; i < 4; i++) qv[i] = Qt[d][ty * 4 + i];
            float kv[8];
            *reinterpret_cast<float4*>(kv)     = *reinterpret_cast<float4*>(&Kt[d][tx * 8]);
            *reinterpret_cast<float4*>(kv + 4) = *reinterpret_cast<float4*>(&Kt[d][tx * 8 + 4]);
#pragma unroll
            for (int i = 0; i < 4; i++)
#pragma unroll
                for (int j = 0; j < 8; j++)
                    s[i][j] = fmaf(qv[i], kv[j], s[i][j]);
        }

        // online softmax (registers; rows shared by tx-group of 8 lanes)
#pragma unroll
        for (int i = 0; i < 4; i++) {
            float mx = s[i][0];
#pragma unroll
            for (int j = 1; j < 8; j++) mx = fmaxf(mx, s[i][j]);
            mx = fmaxf(mx, __shfl_xor_sync(0xffffffffu, mx, 1));
            mx = fmaxf(mx, __shfl_xor_sync(0xffffffffu, mx, 2));
            mx = fmaxf(mx, __shfl_xor_sync(0xffffffffu, mx, 4));
            float mnew = fmaxf(m[i], mx);
            float corr = __expf(m[i] - mnew);
            float rs = 0.f;
#pragma unroll
            for (int j = 0; j < 8; j++) {
                float pv = __expf(s[i][j] - mnew);
                s[i][j] = pv; rs += pv;
            }
            rs += __shfl_xor_sync(0xffffffffu, rs, 1);
            rs += __shfl_xor_sync(0xffffffffu, rs, 2);
            rs += __shfl_xor_sync(0xffffffffu, rs, 4);
            l[i] = l[i] * corr + rs;
            m[i] = mnew;
#pragma unroll
            for (int j = 0; j < 8; j++) o[i][j] *= corr;
        }
        __syncthreads();                 // done reading Kt as K
        // write P transposed into Kt: P[k][q]
#pragma unroll
        for (int i = 0; i < 4; i++)
#pragma unroll
            for (int j = 0; j < 8; j++)
                Kt[tx * 8 + j][ty * 4 + i] = s[i][j];
        __syncthreads();

        // O += P V
#pragma unroll 4
        for (int kc = 0; kc < 64; kc++) {
            float p[4];
#pragma unroll
            for (int i = 0; i < 4; i++) p[i] = Kt[kc][ty * 4 + i];
            float vv[8];
            *reinterpret_cast<float4*>(vv)     = *reinterpret_cast<float4*>(&Vs[kc][tx * 8]);
            *reinterpret_cast<float4*>(vv + 4) = *reinterpret_cast<float4*>(&Vs[kc][tx * 8 + 4]);
#pragma unroll
            for (int i = 0; i < 4; i++)
#pragma unroll
                for (int j = 0; j < 8; j++)
                    o[i][j] = fmaf(p[i], vv[j], o[i][j]);
        }
        __syncthreads();
    }

    // epilogue: normalize and write into (b, n, h*64+d) row layout
    int b = bh / NHEADS, hh = bh % NHEADS;
#pragma unroll
    for (int i = 0; i < 4; i++) {
        float invl = 1.0f / l[i];
        int n = q0 + ty * 4 + i;
        float* orow = O + ((size_t)(b * NSEQ + n)) * DIMM + hh * DHEAD + tx * 8;
#pragma unroll
        for (int j = 0; j < 8; j++) orow[j] = o[i][j] * invl;
    }
}

// ------------------------------ GELU gate -------------------------------------
__global__ void __launch_bounds__(256) gate_kernel(
    const float* __restrict__ u, float* __restrict__ g)
{
    int idx = blockIdx.x * 256 + threadIdx.x;  // 0 .. 4096*2048-1
    int row = idx / FFI;
    int c   = idx - row * FFI;
    float a  = u[(size_t)row * (2 * FFI) + c];
    float xg = u[(size_t)row * (2 * FFI) + FFI + c];
    float gl = 0.5f * xg * (1.0f + erff(xg * 0.7071067811865475f));
    g[idx] = a * gl;
}

// ------------------------------ launch ----------------------------------------
extern "C" void kernel_launch(void* const* d_in, const int* in_sizes, int n_in,
                              void* d_out, int out_size)
{
    (void)in_sizes; (void)n_in; (void)out_size;
    const float* x          = (const float*)d_in[0];
    const float* attn_gamma = (const float*)d_in[1];
    const float* wq         = (const float*)d_in[2];
    const float* wkv        = (const float*)d_in[3];
    const float* q_scale    = (const float*)d_in[4];
    const float* k_scale    = (const float*)d_in[5];
    const float* wo         = (const float*)d_in[6];
    const float* ff_gamma   = (const float*)d_in[7];
    const float* ff_beta    = (const float*)d_in[8];
    const float* wff1       = (const float*)d_in[9];
    const float* wff2       = (const float*)d_in[10];
    float* xo = (float*)d_out;

    float *h, *q, *kv, *qt, *kt, *vt, *o, *u, *g;
    cudaGetSymbolAddress((void**)&h,  g_h);
    cudaGetSymbolAddress((void**)&q,  g_q);
    cudaGetSymbolAddress((void**)&kv, g_kv);
    cudaGetSymbolAddress((void**)&qt, g_qt);
    cudaGetSymbolAddress((void**)&kt, g_kt);
    cudaGetSymbolAddress((void**)&vt, g_vt);
    cudaGetSymbolAddress((void**)&o,  g_o);
    cudaGetSymbolAddress((void**)&u,  g_u);
    cudaGetSymbolAddress((void**)&g,  g_g);

    cudaMemcpyAsync(xo, x, (size_t)MTOK * DIMM * sizeof(float),
                    cudaMemcpyDeviceToDevice);

    for (int i = 0; i < 4; i++) {
        // attention block
        ln_kernel<<<MTOK, 256>>>(xo, attn_gamma + (size_t)i * DIMM, nullptr, h);
        sgemm_kernel<<<dim3(DIMM / BN, MTOK / BM), 256>>>(
            h, wq + (size_t)i * DIMM * DIMM, nullptr, q, MTOK, DIMM, DIMM);
        sgemm_kernel<<<dim3(2 * DIMM / BN, MTOK / BM), 256>>>(
            xo, wkv + (size_t)i * DIMM * 2 * DIMM, nullptr, kv, MTOK, 2 * DIMM, DIMM);
        rope_norm_kernel<<<dim3(MTOK, NHEADS), 64>>>(q, DIMM, q_scale + (size_t)i * DHEAD, qt);
        rope_norm_kernel<<<dim3(MTOK, NHEADS), 64>>>(kv, 2 * DIMM, k_scale + (size_t)i * DHEAD, kt);
        vtrans_kernel<<<(MTOK * DIMM) / 256, 256>>>(kv, vt);
        attn_kernel<<<dim3(NSEQ / 64, BHTOT), 128>>>(qt, kt, vt, o);
        sgemm_kernel<<<dim3(DIMM / BN, MTOK / BM), 256>>>(
            o, wo + (size_t)i * DIMM * DIMM, xo, xo, MTOK, DIMM, DIMM);

        // feed-forward block
        ln_kernel<<<MTOK, 256>>>(xo, ff_gamma + (size_t)i * DIMM,
                                 ff_beta + (size_t)i * DIMM, h);
        sgemm_kernel<<<dim3(2 * FFI / BN, MTOK / BM), 256>>>(
            h, wff1 + (size_t)i * DIMM * 2 * FFI, nullptr, u, MTOK, 2 * FFI, DIMM);
        gate_kernel<<<(MTOK * FFI) / 256, 256>>>(u, g);
        sgemm_kernel<<<dim3(DIMM / BN, MTOK / BM), 256>>>(
            g, wff2 + (size_t)i * FFI * DIMM, xo, xo, MTOK, DIMM, FFI);
    }
}